// round 4
// baseline (speedup 1.0000x reference)
#include <cuda_runtime.h>
#include <cuda_fp16.h>
#include <math.h>
#include <stdint.h>

// ===========================================================================
// PixelateDegradation:  out[b,c] = C_{t[b]} @ x0[b,c] @ C_{t[b]}^T
// mma.sync tensor path, fp16 split precision (D += AhBh + AhBl + AlBh),
// operands pre-split to fp16 hi/lo in gmem, cp.async double-buffered GEMMs.
// ===========================================================================

#define TS 20
#define SZ 256
#define NIMG 192
#define MAXT 12

__device__ __half g_Ch[TS][SZ][SZ];
__device__ __half g_Cl[TS][SZ][SZ];
__device__ __half g_Xth[(size_t)NIMG * SZ * SZ];   // X^T hi  (n-major, k-contig)
__device__ __half g_Xtl[(size_t)NIMG * SZ * SZ];   // X^T lo
__device__ __half g_Yh[(size_t)NIMG * SZ * SZ];    // Y = C@X hi (m-major, k-contig)
__device__ __half g_Yl[(size_t)NIMG * SZ * SZ];
__device__ float g_tw[TS][SZ][MAXT];
__device__ int   g_trow[TS][SZ][MAXT];
__device__ int   g_tn[TS][SZ];

// ---------------------------------------------------------------------------
// Setup: sparse step matrices (float64 build, matches numpy)
// ---------------------------------------------------------------------------
__device__ __forceinline__ double cc1d(double x) {
    const double A = -0.75;
    return ((A + 2.0) * x - (A + 3.0)) * x * x + 1.0;
}
__device__ __forceinline__ double cc2d(double x) {
    const double A = -0.75;
    return ((A * x - 5.0 * A) * x + 8.0 * A) * x - 4.0 * A;
}

__global__ void weights_kernel() {
    int i = blockIdx.x;
    int o = threadIdx.x;
    __shared__ float sw[SZ][4];
    __shared__ int   scol[SZ][4];

    double s = (double)(SZ - i);
    int src = (int)floor((o + 0.5) * s / 256.0);
    int smax = (SZ - i) - 1;
    if (src > smax) src = smax;
    if (src < 0) src = 0;

    double x  = (src + 0.5) * 256.0 / s - 0.5;
    double i0 = floor(x);
    double tt = x - i0;
    double ws[4] = {cc2d(tt + 1.0), cc1d(tt), cc1d(1.0 - tt), cc2d(2.0 - tt)};
    int ib = (int)i0;
#pragma unroll
    for (int k = 0; k < 4; k++) {
        int c = ib - 1 + k;
        if (c < 0) c = 0;
        if (c > SZ - 1) c = SZ - 1;
        scol[o][k] = c;
        sw[o][k]   = (float)ws[k];
    }
    __syncthreads();

    int h = threadIdx.x;
    int cnt = 0;
    for (int r = 0; r < SZ; r++) {
#pragma unroll
        for (int k = 0; k < 4; k++) {
            if (scol[r][k] == h && cnt < MAXT) {
                g_trow[i][h][cnt] = r;
                g_tw[i][h][cnt]   = sw[r][k];
                cnt++;
            }
        }
    }
    g_tn[i][h] = cnt;
}

// prefix products C_t, written directly as fp16 hi/lo
__global__ void chain_kernel() {
    int o = blockIdx.x;
    int t = blockIdx.y;
    int h = threadIdx.x;

    __shared__ float u[SZ];
    u[h] = (h == o) ? 1.0f : 0.0f;
    __syncthreads();

    for (int step = t - 1; step >= 0; --step) {
        int n = g_tn[step][h];
        float acc = 0.0f;
        for (int j = 0; j < n; j++)
            acc += g_tw[step][h][j] * u[g_trow[step][h][j]];
        __syncthreads();
        u[h] = acc;
        __syncthreads();
    }
    float v = u[h];
    __half hv = __float2half_rn(v);
    __half lv = __float2half_rn(v - __half2float(hv));
    g_Ch[t][o][h] = hv;
    g_Cl[t][o][h] = lv;
}

// transpose + split X: Xt[n][k] = X[k][n], fp16 hi/lo
__global__ void xsplit_kernel(const float* __restrict__ x0) {
    __shared__ float s[32][33];
    int img = blockIdx.z;
    int n0 = blockIdx.x * 32, k0 = blockIdx.y * 32;
    const float* X = x0 + (size_t)img * SZ * SZ;
    int tx = threadIdx.x, ty = threadIdx.y;
#pragma unroll
    for (int j = 0; j < 4; j++)
        s[ty + j * 8][tx] = X[(size_t)(k0 + ty + j * 8) * SZ + n0 + tx];
    __syncthreads();
    __half* oh = g_Xth + (size_t)img * SZ * SZ;
    __half* ol = g_Xtl + (size_t)img * SZ * SZ;
#pragma unroll
    for (int j = 0; j < 4; j++) {
        int n = ty + j * 8;
        float v = s[tx][n];
        __half hv = __float2half_rn(v);
        __half lv = __float2half_rn(v - __half2float(hv));
        size_t o = (size_t)(n0 + n) * SZ + k0 + tx;
        oh[o] = hv;
        ol[o] = lv;
    }
}

// ---------------------------------------------------------------------------
// GEMM: 128x128 CTA tile, 4 warps (64x64 each), K-chunk 32, double-buffered
// cp.async. smem sub-tiles (80B row pitch): Ah +0, Al +10240, Bh +20480,
// Bl +30720; buffer stride 40960; total 81920 B.
// ---------------------------------------------------------------------------
static constexpr int SMEM_BYTES = 81920;
static constexpr uint32_t T_AL = 10240;
static constexpr uint32_t T_BH = 20480;
static constexpr uint32_t BUFSTRIDE = 40960;

__device__ __forceinline__ uint32_t smem_to_u32(const void* p) {
    uint32_t a;
    asm("{ .reg .u64 t; cvta.to.shared.u64 t, %1; cvt.u32.u64 %0, t; }"
        : "=r"(a) : "l"(p));
    return a;
}
__device__ __forceinline__ void ldsm_x4(uint32_t r[4], uint32_t addr) {
    asm volatile("ldmatrix.sync.aligned.m8n8.x4.shared.b16 {%0,%1,%2,%3}, [%4];"
                 : "=r"(r[0]), "=r"(r[1]), "=r"(r[2]), "=r"(r[3]) : "r"(addr));
}
__device__ __forceinline__ void mma16816(float d[4], const uint32_t a[4],
                                         const uint32_t b[2]) {
    asm volatile(
        "mma.sync.aligned.m16n8k16.row.col.f32.f16.f16.f32 "
        "{%0,%1,%2,%3}, {%4,%5,%6,%7}, {%8,%9}, {%0,%1,%2,%3};"
        : "+f"(d[0]), "+f"(d[1]), "+f"(d[2]), "+f"(d[3])
        : "r"(a[0]), "r"(a[1]), "r"(a[2]), "r"(a[3]), "r"(b[0]), "r"(b[1]));
}
__device__ __forceinline__ void cp16(uint32_t d, const void* g) {
    asm volatile("cp.async.cg.shared.global [%0], [%1], 16;"
                 :: "r"(d), "l"(g) : "memory");
}
#define CP_COMMIT() asm volatile("cp.async.commit_group;" ::: "memory")
#define CP_WAIT(N)  asm volatile("cp.async.wait_group %0;" :: "n"(N) : "memory")

// stage one k-chunk (A tile 128x32 from rows mb.., B tile 128x32 from rows nb..)
__device__ __forceinline__ void stage_chunk(
    uint32_t buf, const __half* __restrict__ Ah, const __half* __restrict__ Al,
    const __half* __restrict__ Bh, const __half* __restrict__ Bl,
    int mb, int nb, int kc, int tid) {
    int r = tid >> 2;          // 0..31
    int s = tid & 3;           // 16B chunk in row
    uint32_t dst = buf + (uint32_t)(r * 80 + s * 16);
    size_t goff = (size_t)(r)*SZ + kc + s * 8;
    const __half* pah = Ah + (size_t)mb * SZ + goff;
    const __half* pal = Al + (size_t)mb * SZ + goff;
    const __half* pbh = Bh + (size_t)nb * SZ + goff;
    const __half* pbl = Bl + (size_t)nb * SZ + goff;
#pragma unroll
    for (int it = 0; it < 4; it++) {
        size_t g = (size_t)(it * 32) * SZ;
        uint32_t d = dst + it * 32 * 80;
        cp16(d,            pah + g);
        cp16(d + T_AL,     pal + g);
        cp16(d + T_BH,     pbh + g);
        cp16(d + T_BH + T_AL, pbl + g);
    }
}

__device__ __forceinline__ void compute_chunk(uint32_t buf, int warpm, int warpn,
                                              int lane, float acc[4][8][4]) {
    const uint32_t arow = buf +
        (uint32_t)((warpm * 64 + (lane & 15)) * 80 + ((lane & 16) ? 16 : 0));
    const uint32_t brow = buf + T_BH +
        (uint32_t)((warpn * 64 + (lane & 7) + ((lane & 16) ? 8 : 0)) * 80 +
                   ((lane & 8) ? 16 : 0));
#pragma unroll
    for (int K16 = 0; K16 < 2; K16++) {
        uint32_t aH[4][4], aL[4][4];
#pragma unroll
        for (int mt = 0; mt < 4; mt++) {
            uint32_t a = arow + (uint32_t)(mt * 16 * 80 + K16 * 32);
            ldsm_x4(aH[mt], a);
            ldsm_x4(aL[mt], a + T_AL);
        }
#pragma unroll
        for (int g = 0; g < 4; g++) {
            uint32_t bH[4], bL[4];
            uint32_t b = brow + (uint32_t)(g * 16 * 80 + K16 * 32);
            ldsm_x4(bH, b);
            ldsm_x4(bL, b + T_AL);
#pragma unroll
            for (int mt = 0; mt < 4; mt++) {
                mma16816(acc[mt][2 * g],     aH[mt], bH);
                mma16816(acc[mt][2 * g + 1], aH[mt], bH + 2);
                mma16816(acc[mt][2 * g],     aH[mt], bL);
                mma16816(acc[mt][2 * g + 1], aH[mt], bL + 2);
                mma16816(acc[mt][2 * g],     aL[mt], bH);
                mma16816(acc[mt][2 * g + 1], aL[mt], bH + 2);
            }
        }
    }
}

template <bool SPLIT_EPI>
__device__ __forceinline__ void mm_core(
    const __half* __restrict__ Ah, const __half* __restrict__ Al,
    const __half* __restrict__ Bh, const __half* __restrict__ Bl,
    float* __restrict__ Of, __half* __restrict__ Oh, __half* __restrict__ Ol) {
    extern __shared__ char smem[];
    uint32_t sb = smem_to_u32(smem);

    const int tid   = threadIdx.x;
    const int lane  = tid & 31;
    const int wid   = tid >> 5;
    const int warpm = wid & 1;
    const int warpn = wid >> 1;
    const int mb    = blockIdx.y * 128;
    const int nb    = blockIdx.x * 128;

    float acc[4][8][4];
#pragma unroll
    for (int i = 0; i < 4; i++)
#pragma unroll
        for (int j = 0; j < 8; j++)
#pragma unroll
            for (int q = 0; q < 4; q++) acc[i][j][q] = 0.0f;

    stage_chunk(sb, Ah, Al, Bh, Bl, mb, nb, 0, tid);
    CP_COMMIT();
    stage_chunk(sb + BUFSTRIDE, Ah, Al, Bh, Bl, mb, nb, 32, tid);
    CP_COMMIT();

#pragma unroll 1
    for (int c = 0; c < 8; c++) {
        if (c < 7) { CP_WAIT(1); } else { CP_WAIT(0); }
        __syncthreads();
        uint32_t buf = sb + (uint32_t)((c & 1) * BUFSTRIDE);
        compute_chunk(buf, warpm, warpn, lane, acc);
        __syncthreads();
        if (c + 2 < 8) {
            stage_chunk(buf, Ah, Al, Bh, Bl, mb, nb, (c + 2) * 32, tid);
            CP_COMMIT();
        }
    }

    // epilogue
    const int rbase = mb + warpm * 64 + (lane >> 2);
    const int cbase = nb + warpn * 64 + (lane & 3) * 2;
#pragma unroll
    for (int mt = 0; mt < 4; mt++) {
#pragma unroll
        for (int nt = 0; nt < 8; nt++) {
            int col = cbase + nt * 8;
            int r0 = rbase + mt * 16;
            int r1 = r0 + 8;
            float v0 = acc[mt][nt][0], v1 = acc[mt][nt][1];
            float v2 = acc[mt][nt][2], v3 = acc[mt][nt][3];
            if (SPLIT_EPI) {
                __half h0 = __float2half_rn(v0), h1 = __float2half_rn(v1);
                __half h2 = __float2half_rn(v2), h3 = __float2half_rn(v3);
                __half l0 = __float2half_rn(v0 - __half2float(h0));
                __half l1 = __float2half_rn(v1 - __half2float(h1));
                __half l2 = __float2half_rn(v2 - __half2float(h2));
                __half l3 = __float2half_rn(v3 - __half2float(h3));
                *reinterpret_cast<__half2*>(Oh + (size_t)r0 * SZ + col) =
                    __halves2half2(h0, h1);
                *reinterpret_cast<__half2*>(Ol + (size_t)r0 * SZ + col) =
                    __halves2half2(l0, l1);
                *reinterpret_cast<__half2*>(Oh + (size_t)r1 * SZ + col) =
                    __halves2half2(h2, h3);
                *reinterpret_cast<__half2*>(Ol + (size_t)r1 * SZ + col) =
                    __halves2half2(l2, l3);
            } else {
                *reinterpret_cast<float2*>(Of + (size_t)r0 * SZ + col) =
                    make_float2(v0, v1);
                *reinterpret_cast<float2*>(Of + (size_t)r1 * SZ + col) =
                    make_float2(v2, v3);
            }
        }
    }
}

__global__ void __launch_bounds__(128, 2)
phase1_kernel(const int* __restrict__ t) {
    int img = blockIdx.z;
    int tb  = __ldg(&t[img / 3]);
    size_t io = (size_t)img * SZ * SZ;
    mm_core<true>(&g_Ch[tb][0][0], &g_Cl[tb][0][0],
                  g_Xth + io, g_Xtl + io,
                  nullptr, g_Yh + io, g_Yl + io);
}

__global__ void __launch_bounds__(128, 2)
phase2_kernel(float* __restrict__ out, const int* __restrict__ t) {
    int img = blockIdx.z;
    int tb  = __ldg(&t[img / 3]);
    size_t io = (size_t)img * SZ * SZ;
    mm_core<false>(g_Yh + io, g_Yl + io,
                   &g_Ch[tb][0][0], &g_Cl[tb][0][0],
                   out + io, nullptr, nullptr);
}

// ---------------------------------------------------------------------------
extern "C" void kernel_launch(void* const* d_in, const int* in_sizes, int n_in,
                              void* d_out, int out_size) {
    const float* x0 = (const float*)d_in[0];
    const int*   t  = (const int*)d_in[1];
    float* out      = (float*)d_out;

    weights_kernel<<<TS, 256>>>();
    chain_kernel<<<dim3(SZ, TS), 256>>>();
    xsplit_kernel<<<dim3(8, 8, NIMG), dim3(32, 8)>>>(x0);

    cudaFuncSetAttribute(phase1_kernel,
                         cudaFuncAttributeMaxDynamicSharedMemorySize, SMEM_BYTES);
    cudaFuncSetAttribute(phase2_kernel,
                         cudaFuncAttributeMaxDynamicSharedMemorySize, SMEM_BYTES);
    phase1_kernel<<<dim3(2, 2, NIMG), 128, SMEM_BYTES>>>(t);
    phase2_kernel<<<dim3(2, 2, NIMG), 128, SMEM_BYTES>>>(out, t);
}